// round 16
// baseline (speedup 1.0000x reference)
#include <cuda_runtime.h>
#include <cuda_bf16.h>
#include <math.h>
#include <stdint.h>

#define D_MODEL 1024
#define F_FFN   4096
#define B_SZ    4
#define S_LEN   2048
#define N_HEADS 16
#define DK      64
#define M_ROWS  (B_SZ * S_LEN)
#define LN_EPS  1e-6f
#define QKV_N   3072

#define ACT_S   (6.0f / 127.0f)
#define ACT_IS  (127.0f / 6.0f)
#define W1_S    (0.1875f / 127.0f)
#define W1_IS   (127.0f / 0.1875f)
#define W2_S    (0.09375f / 127.0f)
#define W2_IS   (127.0f / 0.09375f)

typedef __nv_bfloat16 bf16;

// ---------------- scratch ----------------
__device__ bf16 g_xn_h [(size_t)M_ROWS * D_MODEL];
__device__ bf16 g_xn_l [(size_t)M_ROWS * D_MODEL];
__device__ bf16 g_qkv_h[(size_t)M_ROWS * QKV_N];
__device__ bf16 g_qkv_l[(size_t)M_ROWS * QKV_N];
__device__ bf16 g_ctx_h[(size_t)M_ROWS * D_MODEL];
__device__ bf16 g_ctx_l[(size_t)M_ROWS * D_MODEL];
__device__ float g_hbuf[(size_t)M_ROWS * D_MODEL];
__device__ int8_t g_xn28h[(size_t)M_ROWS * D_MODEL];
__device__ int8_t g_xn28l[(size_t)M_ROWS * D_MODEL];
__device__ int8_t g_mid8h[(size_t)M_ROWS * F_FFN];
__device__ int8_t g_mid8l[(size_t)M_ROWS * F_FFN];
__device__ bf16 g_wqkv_h[(size_t)D_MODEL * QKV_N];
__device__ bf16 g_wqkv_l[(size_t)D_MODEL * QKV_N];
__device__ float g_bqkv[QKV_N];
__device__ bf16 g_wo_h[(size_t)D_MODEL * D_MODEL];
__device__ bf16 g_wo_l[(size_t)D_MODEL * D_MODEL];
__device__ int8_t g_w18h[(size_t)D_MODEL * F_FFN];
__device__ int8_t g_w18l[(size_t)D_MODEL * F_FFN];
__device__ int8_t g_w28h[(size_t)F_FFN * D_MODEL];
__device__ int8_t g_w28l[(size_t)F_FFN * D_MODEL];

// ---------------- helpers ----------------
__device__ __forceinline__ uint32_t smem_u32(const void* p) {
    return (uint32_t)__cvta_generic_to_shared(p);
}
#define LDSM_X4(r0,r1,r2,r3,addr) \
    asm volatile("ldmatrix.sync.aligned.m8n8.x4.shared.b16 {%0,%1,%2,%3},[%4];" \
        : "=r"(r0), "=r"(r1), "=r"(r2), "=r"(r3) : "r"(addr))
#define LDSM_X4T(r0,r1,r2,r3,addr) \
    asm volatile("ldmatrix.sync.aligned.m8n8.x4.trans.shared.b16 {%0,%1,%2,%3},[%4];" \
        : "=r"(r0), "=r"(r1), "=r"(r2), "=r"(r3) : "r"(addr))
#define MMA16816(c,a,b0,b1) \
    asm volatile("mma.sync.aligned.m16n8k16.row.col.f32.bf16.bf16.f32 " \
        "{%0,%1,%2,%3},{%4,%5,%6,%7},{%8,%9},{%0,%1,%2,%3};" \
        : "+f"((c)[0]), "+f"((c)[1]), "+f"((c)[2]), "+f"((c)[3]) \
        : "r"((a)[0]), "r"((a)[1]), "r"((a)[2]), "r"((a)[3]), "r"(b0), "r"(b1))
#define QMMA(d,a,b) \
    asm volatile("mma.sync.aligned.m16n8k32.row.col.s32.s8.s8.s32 " \
        "{%0,%1,%2,%3},{%4,%5,%6,%7},{%8,%9},{%0,%1,%2,%3};" \
        : "+r"((d)[0]), "+r"((d)[1]), "+r"((d)[2]), "+r"((d)[3]) \
        : "r"((a)[0]), "r"((a)[1]), "r"((a)[2]), "r"((a)[3]), "r"((b)[0]), "r"((b)[1]))
#define LDS32(r, addr) asm volatile("ld.shared.b32 %0,[%1];" : "=r"(r) : "r"(addr))
#define CP16(dst, src) \
    asm volatile("cp.async.cg.shared.global [%0],[%1],16;" :: "r"(dst), "l"(src))
#define CP_COMMIT asm volatile("cp.async.commit_group;")
#define CP_WAIT1  asm volatile("cp.async.wait_group 1;")
#define CP_WAIT0  asm volatile("cp.async.wait_group 0;")

__device__ __forceinline__ void split2(float x, bf16& h, bf16& l) {
    h = __float2bfloat16(x);
    l = __float2bfloat16(x - __bfloat162float(h));
}
__device__ __forceinline__ void pack_hl(float x, float y, uint32_t& h, uint32_t& l) {
    bf16 hx, lx, hy, ly;
    split2(x, hx, lx); split2(y, hy, ly);
    __nv_bfloat162 hp = __halves2bfloat162(hx, hy);
    __nv_bfloat162 lp = __halves2bfloat162(lx, ly);
    h = *(uint32_t*)&hp; l = *(uint32_t*)&lp;
}
__device__ __forceinline__ void split_store4(const float4 f, bf16* oh, bf16* ol) {
    __align__(8) bf16 h4[4], l4[4];
    split2(f.x, h4[0], l4[0]); split2(f.y, h4[1], l4[1]);
    split2(f.z, h4[2], l4[2]); split2(f.w, h4[3], l4[3]);
    *(uint2*)oh = *(uint2*)h4; *(uint2*)ol = *(uint2*)l4;
}
__device__ __forceinline__ void quant8(float x, float invS, float S, int& h, int& l) {
    float qh = rintf(x * invS);
    qh = fminf(127.f, fmaxf(-127.f, qh));
    h = (int)qh;
    float ql = rintf((x - qh * S) * (invS * 254.f));
    ql = fminf(127.f, fmaxf(-127.f, ql));
    l = (int)ql;
}

// ---------------- weight prep ----------------
__global__ void __launch_bounds__(256) split_qkv_kernel(
    const float* __restrict__ wq, const float* __restrict__ wk,
    const float* __restrict__ wv,
    const float* __restrict__ bq, const float* __restrict__ bk,
    const float* __restrict__ bv,
    bf16* __restrict__ oh, bf16* __restrict__ ol, float* __restrict__ bqkv)
{
    const size_t gid = ((size_t)blockIdx.x * 256 + threadIdx.x) * 4;
    const int row = (int)(gid / QKV_N);
    const int col = (int)(gid % QKV_N);
    const float* src; int scol;
    if (col < 1024)      { src = wq; scol = col; }
    else if (col < 2048) { src = wk; scol = col - 1024; }
    else                 { src = wv; scol = col - 2048; }
    const float4 f = *(const float4*)(src + (size_t)row * D_MODEL + scol);
    split_store4(f, oh + gid, ol + gid);
    if (gid < QKV_N) {
        #pragma unroll
        for (int i = 0; i < 4; i++) {
            const int c = (int)gid + i;
            bqkv[c] = (c < 1024) ? bq[c] : ((c < 2048) ? bk[c - 1024] : bv[c - 2048]);
        }
    }
}

__global__ void __launch_bounds__(256) split_wo_kernel(
    const float* __restrict__ wo, bf16* __restrict__ oh, bf16* __restrict__ ol)
{
    const size_t i = ((size_t)blockIdx.x * 256 + threadIdx.x) * 4;
    const float4 f = *(const float4*)(wo + i);
    split_store4(f, oh + i, ol + i);
}

// quantize W[K,N] -> interleaved [K/4][N][4] int8 hi/lo
__global__ void __launch_bounds__(256) quantw_kernel(
    const float* __restrict__ src, int8_t* __restrict__ dh,
    int8_t* __restrict__ dl, int N, float invS, float S)
{
    const size_t linear = (size_t)blockIdx.x * 256 + threadIdx.x;
    const int n  = (int)(linear % N);
    const int k4 = (int)(linear / N);
    uint32_t ph = 0, pl = 0;
    #pragma unroll
    for (int j = 0; j < 4; j++) {
        const float v = src[(size_t)(k4 * 4 + j) * N + n];
        int h, l;
        quant8(v, invS, S, h, l);
        ph |= ((uint32_t)(uint8_t)(int8_t)h) << (8 * j);
        pl |= ((uint32_t)(uint8_t)(int8_t)l) << (8 * j);
    }
    ((uint32_t*)dh)[linear] = ph;
    ((uint32_t*)dl)[linear] = pl;
}

// ---------------- LayerNorm variants ----------------
__device__ __forceinline__ void ln_core(const float4 v, int tid, float* red,
                                        float& mean, float& inv)
{
    float s  = v.x + v.y + v.z + v.w;
    float s2 = v.x*v.x + v.y*v.y + v.z*v.z + v.w*v.w;
    #pragma unroll
    for (int off = 16; off > 0; off >>= 1) {
        s  += __shfl_xor_sync(0xffffffffu, s,  off);
        s2 += __shfl_xor_sync(0xffffffffu, s2, off);
    }
    const int warp = tid >> 5;
    if ((tid & 31) == 0) { red[warp] = s; red[8 + warp] = s2; }
    __syncthreads();
    if (tid == 0) {
        float ts = 0.f, ts2 = 0.f;
        #pragma unroll
        for (int i = 0; i < 8; i++) { ts += red[i]; ts2 += red[8 + i]; }
        const float m = ts * (1.0f / (float)D_MODEL);
        float var = (ts2 - (float)D_MODEL * m * m) * (1.0f / (float)(D_MODEL - 1));
        var = fmaxf(var, 0.0f);
        red[16] = m;
        red[17] = 1.0f / (sqrtf(var) + LN_EPS);
    }
    __syncthreads();
    mean = red[16]; inv = red[17];
}

__global__ void __launch_bounds__(256) ln_split_kernel(
    const float* __restrict__ x, const float* __restrict__ alpha,
    const float* __restrict__ beta, bf16* __restrict__ oh, bf16* __restrict__ ol)
{
    __shared__ float red[32];
    const int row = blockIdx.x, tid = threadIdx.x;
    const float4 v = ((const float4*)(x + (size_t)row * D_MODEL))[tid];
    float mean, inv;
    ln_core(v, tid, red, mean, inv);
    const float4 a = ((const float4*)alpha)[tid];
    const float4 b = ((const float4*)beta)[tid];
    float4 o;
    o.x = a.x * (v.x - mean) * inv + b.x;
    o.y = a.y * (v.y - mean) * inv + b.y;
    o.z = a.z * (v.z - mean) * inv + b.z;
    o.w = a.w * (v.w - mean) * inv + b.w;
    split_store4(o, oh + (size_t)row * D_MODEL + tid * 4,
                    ol + (size_t)row * D_MODEL + tid * 4);
}

__global__ void __launch_bounds__(256) ln_quant_kernel(
    const float* __restrict__ x, const float* __restrict__ alpha,
    const float* __restrict__ beta, int8_t* __restrict__ oh, int8_t* __restrict__ ol)
{
    __shared__ float red[32];
    const int row = blockIdx.x, tid = threadIdx.x;
    const float4 v = ((const float4*)(x + (size_t)row * D_MODEL))[tid];
    float mean, inv;
    ln_core(v, tid, red, mean, inv);
    const float4 a = ((const float4*)alpha)[tid];
    const float4 b = ((const float4*)beta)[tid];
    float o[4];
    o[0] = a.x * (v.x - mean) * inv + b.x;
    o[1] = a.y * (v.y - mean) * inv + b.y;
    o[2] = a.z * (v.z - mean) * inv + b.z;
    o[3] = a.w * (v.w - mean) * inv + b.w;
    uint32_t ph = 0, pl = 0;
    #pragma unroll
    for (int j = 0; j < 4; j++) {
        int h, l;
        quant8(o[j], ACT_IS, ACT_S, h, l);
        ph |= ((uint32_t)(uint8_t)(int8_t)h) << (8 * j);
        pl |= ((uint32_t)(uint8_t)(int8_t)l) << (8 * j);
    }
    ((uint32_t*)oh)[(size_t)row * 256 + tid] = ph;
    ((uint32_t*)ol)[(size_t)row * 256 + tid] = pl;
}

// ---------------- bf16 GEMM (QKV, o-proj) — R12 config ----------------------
#define ASTR 40
#define BSTR 136
#define STAGE_A (128 * ASTR)
#define STAGE_B (32 * BSTR)
#define STAGE_ELEMS (2 * STAGE_A + 2 * STAGE_B)
#define GEMM_SMEM (2 * STAGE_ELEMS * 2)

template<bool RES, bool BF16OUT>
__global__ void __launch_bounds__(256, 2) mma_gemm(
    const bf16* __restrict__ Ah, const bf16* __restrict__ Al,
    const bf16* __restrict__ Bh, const bf16* __restrict__ Bl,
    const float* __restrict__ bias, const float* __restrict__ res,
    float* __restrict__ C, bf16* __restrict__ Ch, bf16* __restrict__ Cl,
    int M, int N, int K)
{
    extern __shared__ bf16 sm[];
    const int tid  = threadIdx.x;
    const int lane = tid & 31;
    const int wid  = tid >> 5;
    const int wm   = (wid & 3) * 32;
    const int wn   = (wid >> 2) * 64;
    const int bx = blockIdx.x, by = blockIdx.y;

    const bf16* Abh = Ah + (size_t)(by * 128) * K;
    const bf16* Abl = Al + (size_t)(by * 128) * K;
    const bf16* Bbh = Bh + bx * 128;
    const bf16* Bbl = Bl + bx * 128;

    const int a_row = tid >> 1, a_c = (tid & 1) * 16;
    const int b_row = tid >> 3, b_c = (tid & 7) * 16;

    const uint32_t s_base = smem_u32(sm);
    const uint32_t a_dst0 = (uint32_t)(a_row * ASTR + a_c) * 2;
    const uint32_t b_dst0 = (uint32_t)(2 * STAGE_A + b_row * BSTR + b_c) * 2;

    const int lane16 = lane & 15;
    const int lane8  = (lane >> 4) * 8;
    const uint32_t a_off = (uint32_t)(((wm + lane16) * ASTR + lane8) * 2);
    const uint32_t b_off = (uint32_t)((lane16 * BSTR + wn + lane8) * 2);

    float acc[2][8][4];
    #pragma unroll
    for (int i = 0; i < 2; i++)
        #pragma unroll
        for (int j = 0; j < 8; j++)
            #pragma unroll
            for (int q = 0; q < 4; q++) acc[i][j][q] = 0.f;

    const int NT = K >> 5;
    {
        const uint32_t so = s_base;
        CP16(so + a_dst0,      Abh + (size_t)a_row * K + a_c);
        CP16(so + a_dst0 + 16, Abh + (size_t)a_row * K + a_c + 8);
        CP16(so + a_dst0 + STAGE_A * 2,      Abl + (size_t)a_row * K + a_c);
        CP16(so + a_dst0 + STAGE_A * 2 + 16, Abl + (size_t)a_row * K + a_c + 8);
        CP16(so + b_dst0,      Bbh + (size_t)b_row * N + b_c);
        CP16(so + b_dst0 + 16, Bbh + (size_t)b_row * N + b_c + 8);
        CP16(so + b_dst0 + STAGE_B * 2,      Bbl + (size_t)b_row * N + b_c);
        CP16(so + b_dst0 + STAGE_B * 2 + 16, Bbl + (size_t)b_row * N + b_c + 8);
        CP_COMMIT;
    }

    for (int t = 0; t < NT; t++) {
        if (t + 1 < NT) {
            const uint32_t so = s_base + (uint32_t)(((t + 1) & 1) * STAGE_ELEMS * 2);
            const int kt = (t + 1) * 32;
            CP16(so + a_dst0,      Abh + (size_t)a_row * K + kt + a_c);
            CP16(so + a_dst0 + 16, Abh + (size_t)a_row * K + kt + a_c + 8);
            CP16(so + a_dst0 + STAGE_A * 2,      Abl + (size_t)a_row * K + kt + a_c);
            CP16(so + a_dst0 + STAGE_A * 2 + 16, Abl + (size_t)a_row * K + kt + a_c + 8);
            CP16(so + b_dst0,      Bbh + (size_t)(kt + b_row) * N + b_c);
            CP16(so + b_dst0 + 16, Bbh + (size_t)(kt + b_row) * N + b_c + 8);
            CP16(so + b_dst0 + STAGE_B * 2,      Bbl + (size_t)(kt + b_row) * N + b_c);
            CP16(so + b_dst0 + STAGE_B * 2 + 16, Bbl + (size_t)(kt + b_row) * N + b_c + 8);
            CP_COMMIT;
            CP_WAIT1;
        } else {
            CP_WAIT0;
        }
        __syncthreads();

        const uint32_t ash = s_base + (uint32_t)((t & 1) * STAGE_ELEMS * 2);
        const uint32_t asl = ash + STAGE_A * 2;
        const uint32_t bsh = asl + STAGE_A * 2;
        const uint32_t bsl = bsh + STAGE_B * 2;

        #pragma unroll
        for (int ks = 0; ks < 2; ks++) {
            uint32_t ahf[2][4], alf[2][4];
            #pragma unroll
            for (int mf = 0; mf < 2; mf++) {
                const uint32_t ao = a_off + (uint32_t)((mf * 16 * ASTR + ks * 16) * 2);
                LDSM_X4(ahf[mf][0], ahf[mf][1], ahf[mf][2], ahf[mf][3], ash + ao);
                LDSM_X4(alf[mf][0], alf[mf][1], alf[mf][2], alf[mf][3], asl + ao);
            }
            #pragma unroll
            for (int nf2 = 0; nf2 < 4; nf2++) {
                uint32_t bh[4], bl[4];
                const uint32_t bo = b_off + (uint32_t)((ks * 16 * BSTR + nf2 * 16) * 2);
                LDSM_X4T(bh[0], bh[1], bh[2], bh[3], bsh + bo);
                LDSM_X4T(bl[0], bl[1], bl[2], bl[3], bsl + bo);
                #pragma unroll
                for (int mf = 0; mf < 2; mf++) {
                    #pragma unroll
                    for (int hh = 0; hh < 2; hh++) {
                        float* c = acc[mf][nf2 * 2 + hh];
                        MMA16816(c, ahf[mf], bh[2 * hh], bh[2 * hh + 1]);
                        MMA16816(c, ahf[mf], bl[2 * hh], bl[2 * hh + 1]);
                        MMA16816(c, alf[mf], bh[2 * hh], bh[2 * hh + 1]);
                    }
                }
            }
        }
        __syncthreads();
    }

    const int g = lane >> 2, t4 = lane & 3;
    #pragma unroll
    for (int mf = 0; mf < 2; mf++) {
        #pragma unroll
        for (int nf = 0; nf < 8; nf++) {
            const int col = bx * 128 + wn + nf * 8 + t4 * 2;
            const float2 bb = *(const float2*)(bias + col);
            #pragma unroll
            for (int half = 0; half < 2; half++) {
                const size_t r = (size_t)(by * 128 + wm + mf * 16 + g + half * 8);
                float2 o;
                o.x = acc[mf][nf][half * 2 + 0] + bb.x;
                o.y = acc[mf][nf][half * 2 + 1] + bb.y;
                if (RES) {
                    const float2 rv = *(const float2*)(res + r * N + col);
                    o.x += rv.x; o.y += rv.y;
                }
                if (BF16OUT) {
                    uint32_t hw, lw;
                    pack_hl(o.x, o.y, hw, lw);
                    *(uint32_t*)(Ch + r * N + col) = hw;
                    *(uint32_t*)(Cl + r * N + col) = lw;
                } else {
                    *(float2*)(C + r * N + col) = o;
                }
            }
        }
    }
}

// ---------------- int8 GEMM (FFN) --------------------------------------------
// CTA 128x64, K-tile 32, 256 thr = 8 warps (4M x 2N), warp tile 32x32.
// A row-major int8 hi/lo; B interleaved [K/4][N][4] hi/lo.
// D = F1*(HH + (HL+LH)/254) + bias [+res][relu]; OUT8: int8 hi/lo out.
#define QASTR 48
#define QBSTR 288
#define QST_A (128 * QASTR)
#define QST_B (8 * QBSTR)
#define QSTAGE (2 * QST_A + 2 * QST_B)
#define QGEMM_SMEM (2 * QSTAGE)

template<bool RELU, bool RES, bool OUT8>
__global__ void __launch_bounds__(256, 2) qgemm(
    const int8_t* __restrict__ A8h, const int8_t* __restrict__ A8l,
    const int8_t* __restrict__ B8h, const int8_t* __restrict__ B8l,
    const float* __restrict__ bias, const float* __restrict__ res,
    float* __restrict__ C, int8_t* __restrict__ C8h, int8_t* __restrict__ C8l,
    float F1, int M, int N, int K)
{
    extern __shared__ char qsm[];
    const int tid  = threadIdx.x;
    const int lane = tid & 31;
    const int wid  = tid >> 5;
    const int wm   = (wid & 3) * 32;
    const int wn   = (wid >> 2) * 32;
    const int bx = blockIdx.x, by = blockIdx.y;
    const int g  = lane >> 2;
    const int t4 = lane & 3;

    const uint32_t s_base = smem_u32(qsm);

    const int a_row = tid >> 1, a_half = tid & 1;
    const uint32_t a_dst0 = (uint32_t)(a_row * QASTR + a_half * 16);
    const int b_hl = tid >> 7;
    const int b_kg = (tid >> 4) & 7;
    const int b_c  = tid & 15;
    const uint32_t b_dst0 = (uint32_t)(2 * QST_A + b_hl * QST_B + b_kg * QBSTR + b_c * 16);
    const size_t a_g = (size_t)(by * 128 + a_row) * K + a_half * 16;
    const size_t b_g0 = (size_t)bx * 256 + (size_t)b_c * 16;
    const int8_t* Bsrc = b_hl ? B8l : B8h;
    const size_t brow_bytes = (size_t)N * 4;

    int hh[2][4][4], cx[2][4][4];
    #pragma unroll
    for (int i = 0; i < 2; i++)
        #pragma unroll
        for (int j = 0; j < 4; j++)
            #pragma unroll
            for (int q = 0; q < 4; q++) { hh[i][j][q] = 0; cx[i][j][q] = 0; }

    const int NT = K >> 5;
    {
        CP16(s_base + a_dst0,         A8h + a_g);
        CP16(s_base + a_dst0 + QST_A, A8l + a_g);
        CP16(s_base + b_dst0, Bsrc + (size_t)b_kg * brow_bytes + b_g0);
        CP_COMMIT;
    }

    for (int t = 0; t < NT; t++) {
        if (t + 1 < NT) {
            const uint32_t so = s_base + (uint32_t)(((t + 1) & 1) * QSTAGE);
            const int kt = (t + 1) * 32;
            CP16(so + a_dst0,         A8h + a_g + kt);
            CP16(so + a_dst0 + QST_A, A8l + a_g + kt);
            CP16(so + b_dst0, Bsrc + (size_t)((kt >> 2) + b_kg) * brow_bytes + b_g0);
            CP_COMMIT;
            CP_WAIT1;
        } else {
            CP_WAIT0;
        }
        __syncthreads();

        const uint32_t ash = s_base + (uint32_t)((t & 1) * QSTAGE);
        const uint32_t asl = ash + QST_A;
        const uint32_t bsh = asl + QST_A;
        const uint32_t bsl = bsh + QST_B;

        uint32_t ah[2][4], al[2][4];
        #pragma unroll
        for (int mf = 0; mf < 2; mf++) {
            const uint32_t r0 = (uint32_t)((wm + mf * 16 + g) * QASTR + t4 * 4);
            const uint32_t r1 = (uint32_t)((wm + mf * 16 + g + 8) * QASTR + t4 * 4);
            LDS32(ah[mf][0], ash + r0);
            LDS32(ah[mf][1], ash + r1);
            LDS32(ah[mf][2], ash + r0 + 16);
            LDS32(ah[mf][3], ash + r1 + 16);
            LDS32(al[mf][0], asl + r0);
            LDS32(al[mf][1], asl + r1);
            LDS32(al[mf][2], asl + r0 + 16);
            LDS32(al[mf][3], asl + r1 + 16);
        }
        #pragma unroll
        for (int nf = 0; nf < 4; nf++) {
            const uint32_t colw = (uint32_t)((wn + nf * 8 + g) * 4);
            uint32_t bh[2], bl[2];
            LDS32(bh[0], bsh + (uint32_t)(t4 * QBSTR) + colw);
            LDS32(bh[1], bsh + (uint32_t)((t4 + 4) * QBSTR) + colw);
            LDS32(bl[0], bsl + (uint32_t)(t4 * QBSTR) + colw);
            LDS32(bl[1], bsl + (uint32_t)((t4 + 4) * QBSTR) + colw);
            #pragma unroll
            for (int mf = 0; mf < 2; mf++) {
                QMMA(hh[mf][nf], ah[mf], bh);
                QMMA(cx[mf][nf], ah[mf], bl);
                QMMA(cx[mf][nf], al[mf], bh);
            }
        }
        __syncthreads();
    }

    #pragma unroll
    for (int mf = 0; mf < 2; mf++) {
        #pragma unroll
        for (int nf = 0; nf < 4; nf++) {
            const int col = bx * 64 + wn + nf * 8 + t4 * 2;
            const float2 bb = *(const float2*)(bias + col);
            #pragma unroll
            for (int half = 0; half < 2; half++) {
                const size_t r = (size_t)(by * 128 + wm + mf * 16 + g + half * 8);
                float v0 = F1 * fmaf((float)cx[mf][nf][half*2+0], (1.f/254.f),
                                     (float)hh[mf][nf][half*2+0]) + bb.x;
                float v1 = F1 * fmaf((float)cx[mf][nf][half*2+1], (1.f/254.f),
                                     (float)hh[mf][nf][half*2+1]) + bb.y;
                if (RES) {
                    const float2 rv = *(const float2*)(res + r * N + col);
                    v0 += rv.x; v1 += rv.y;
                }
                if (RELU) { v0 = fmaxf(v0, 0.f); v1 = fmaxf(v1, 0.f); }
                if (OUT8) {
                    int h0, l0, h1, l1;
                    quant8(v0, ACT_IS, ACT_S, h0, l0);
                    quant8(v1, ACT_IS, ACT_S, h1, l1);
                    *(uint16_t*)(C8h + r * N + col) = (uint16_t)((uint8_t)(int8_t)h0
                        | ((uint16_t)(uint8_t)(int8_t)h1 << 8));
                    *(uint16_t*)(C8l + r * N + col) = (uint16_t)((uint8_t)(int8_t)l0
                        | ((uint16_t)(uint8_t)(int8_t)l1 << 8));
                } else {
                    float2 o; o.x = v0; o.y = v1;
                    *(float2*)(C + r * N + col) = o;
                }
            }
        }
    }
}

// ---------------- flash attention (R14, unchanged) ---------------------------
#define AQS 72
#define Q_BYTES   (256 * AQS * 2)
#define KV_MAT    (64 * AQS * 2)
#define KV_STAGE  (4 * KV_MAT)
#define MS_OFF    (2 * Q_BYTES + 3 * KV_STAGE)
#define ATTN_SMEM_B (MS_OFF + 3 * 64 * 4)

__global__ void __launch_bounds__(256) attn_mma(
    const bf16* __restrict__ QKVh, const bf16* __restrict__ QKVl,
    const int* __restrict__ mask,
    bf16* __restrict__ Oh, bf16* __restrict__ Ol)
{
    extern __shared__ char smraw[];
    const uint32_t s_base = smem_u32(smraw);
    bf16* Qhs = (bf16*)smraw;
    bf16* Qls = (bf16*)(smraw + Q_BYTES);

    const int b  = blockIdx.z;
    const int h  = blockIdx.y;
    const int q0 = blockIdx.x * 256;
    const int tid  = threadIdx.x;
    const int lane = tid & 31;
    const int wid  = tid >> 5;
    const int lane16 = lane & 15;
    const int lane8  = (lane >> 4) * 8;
    const int g  = lane >> 2;
    const int t2 = (lane & 3) * 2;

    const bf16* Qh = QKVh;
    const bf16* Ql = QKVl;
    const bf16* Kh = QKVh + 1024;
    const bf16* Kl = QKVl + 1024;
    const bf16* Vh = QKVh + 2048;
    const bf16* Vl = QKVl + 2048;

    const uint32_t qsh = s_base;
    const uint32_t qsl = s_base + Q_BYTES;

    const int kv_r = tid >> 2;
    const int kv_c = (tid & 3) * 16;
    const uint32_t kv_dst0 = (uint32_t)((kv_r * AQS + kv_c) * 2);

    #pragma unroll
    for (int s = 0; s < 2; s++) {
        const uint32_t so = s_base + 2 * Q_BYTES + (uint32_t)(s * KV_STAGE);
        const int kt = s * 64;
        const size_t go = ((size_t)(b * S_LEN + kt + kv_r)) * QKV_N + h * DK + kv_c;
        #pragma unroll
        for (int i = 0; i < 2; i++) {
            CP16(so + kv_dst0 + i * 16,              Kh + go + i * 8);
            CP16(so + KV_MAT + kv_dst0 + i * 16,     Kl + go + i * 8);
            CP16(so + 2 * KV_MAT + kv_dst0 + i * 16, Vh + go + i * 8);
            CP16(so + 3 * KV_MAT + kv_dst0 + i * 16, Vl + go + i * 8);
        }
        if (tid < 16)
            CP16(s_base + MS_OFF + (uint32_t)(s * 256 + tid * 16),
                 mask + b * S_LEN + kt + tid * 4);
        CP_COMMIT;
    }

    {
        const int r = tid;
        const size_t go = ((size_t)(b * S_LEN + q0 + r)) * QKV_N + h * DK;
        #pragma unroll
        for (int i = 0; i < 8; i++) {
            *(uint4*)&Qhs[r * AQS + i * 8] = *(const uint4*)(Qh + go + i * 8);
            *(uint4*)&Qls[r * AQS + i * 8] = *(const uint4*)(Ql + go + i * 8);
        }
    }
    __syncthreads();

    float accO[2][8][4];
    #pragma unroll
    for (int mf = 0; mf < 2; mf++)
        #pragma unroll
        for (int j = 0; j < 8; j++)
            #pragma unroll
            for (int q = 0; q < 4; q++) accO[mf][j][q] = 0.f;
    float mrow[2][2] = {{-1e30f, -1e30f}, {-1e30f, -1e30f}};
    float lrow[2][2] = {{0.f, 0.f}, {0.f, 0.f}};

    const int NTK = S_LEN / 64;

    for (int t = 0; t < NTK; t++) {
        CP_WAIT1;
        __syncthreads();

        if (t + 2 < NTK) {
            const uint32_t so = s_base + 2 * Q_BYTES + (uint32_t)(((t + 2) % 3) * KV_STAGE);
            const int kt = (t + 2) * 64;
            const size_t go = ((size_t)(b * S_LEN + kt + kv_r)) * QKV_N + h * DK + kv_c;
            #pragma unroll
            for (int i = 0; i < 2; i++) {
                CP16(so + kv_dst0 + i * 16,              Kh + go + i * 8);
                CP16(so + KV_MAT + kv_dst0 + i * 16,     Kl + go + i * 8);
                CP16(so + 2 * KV_MAT + kv_dst0 + i * 16, Vh + go + i * 8);
                CP16(so + 3 * KV_MAT + kv_dst0 + i * 16, Vl + go + i * 8);
            }
            if (tid < 16)
                CP16(s_base + MS_OFF + (uint32_t)(((t + 2) % 3) * 256 + tid * 16),
                     mask + b * S_LEN + kt + tid * 4);
        }
        CP_COMMIT;

        const int st = t % 3;
        const uint32_t ksh = s_base + 2 * Q_BYTES + (uint32_t)(st * KV_STAGE);
        const uint32_t ksl = ksh + KV_MAT;
        const uint32_t vsh = ksl + KV_MAT;
        const uint32_t vsl = vsh + KV_MAT;
        const int* Msi = (const int*)(smraw + MS_OFF + st * 256);

        float sc[2][8][4];
        #pragma unroll
        for (int mf = 0; mf < 2; mf++)
            #pragma unroll
            for (int j = 0; j < 8; j++)
                #pragma unroll
                for (int q = 0; q < 4; q++) sc[mf][j][q] = 0.f;

        #pragma unroll
        for (int kc = 0; kc < 4; kc++) {
            uint32_t qh[2][4], ql[2][4];
            #pragma unroll
            for (int mf = 0; mf < 2; mf++) {
                const uint32_t qo = (uint32_t)(((wid * 32 + mf * 16 + lane16) * AQS
                                               + kc * 16 + lane8) * 2);
                LDSM_X4(qh[mf][0], qh[mf][1], qh[mf][2], qh[mf][3], qsh + qo);
                LDSM_X4(ql[mf][0], ql[mf][1], ql[mf][2], ql[mf][3], qsl + qo);
            }
            #pragma unroll
            for (int np = 0; np < 4; np++) {
                uint32_t kh[4], kl[4];
                const uint32_t ko = (uint32_t)(((np * 16 + lane16) * AQS
                                               + kc * 16 + lane8) * 2);
                LDSM_X4(kh[0], kh[1], kh[2], kh[3], ksh + ko);
                LDSM_X4(kl[0], kl[1], kl[2], kl[3], ksl + ko);
                #pragma unroll
                for (int mf = 0; mf < 2; mf++) {
                    MMA16816(sc[mf][2*np],   qh[mf], kh[0], kh[2]);
                    MMA16816(sc[mf][2*np],   qh[mf], kl[0], kl[2]);
                    MMA16816(sc[mf][2*np],   ql[mf], kh[0], kh[2]);
                    MMA16816(sc[mf][2*np+1], qh[mf], kh[1], kh[3]);
                    MMA16816(sc[mf][2*np+1], qh[mf], kl[1], kl[3]);
                    MMA16816(sc[mf][2*np+1], ql[mf], kh[1], kh[3]);
                }
            }
        }

        float mb0[8], mb1[8];
        #pragma unroll
        for (int j = 0; j < 8; j++) {
            mb0[j] = (Msi[j * 8 + t2]     == 0) ? -1e9f : 0.f;
            mb1[j] = (Msi[j * 8 + t2 + 1] == 0) ? -1e9f : 0.f;
        }

        #pragma unroll
        for (int mf = 0; mf < 2; mf++) {
            #pragma unroll
            for (int r = 0; r < 2; r++) {
                float mx = -1e30f;
                #pragma unroll
                for (int j = 0; j < 8; j++) {
                    sc[mf][j][2*r]   = sc[mf][j][2*r]   * 0.125f + mb0[j];
                    sc[mf][j][2*r+1] = sc[mf][j][2*r+1] * 0.125f + mb1[j];
                    mx = fmaxf(mx, fmaxf(sc[mf][j][2*r], sc[mf][j][2*r+1]));
                }
                mx = fmaxf(mx, __shfl_xor_sync(0xffffffffu, mx, 1));
                mx = fmaxf(mx, __shfl_xor_sync(0xffffffffu, mx, 2));
                const float nm = fmaxf(mrow[mf][r], mx);
                const float f  = __expf(mrow[mf][r] - nm);
                mrow[mf][r] = nm;
                float sum = 0.f;
                #pragma unroll
                for (int j = 0; j < 8; j++) {
                    sc[mf][j][2*r]   = __expf(sc[mf][j][2*r]   - nm);
                    sc[mf][j][2*r+1] = __expf(sc[mf][j][2*r+1] - nm);
                    sum += sc[mf][j][2*r] + sc[mf][j][2*r+1];
                }
                sum += __shfl_xor_sync(0xffffffffu, sum, 1);
                sum += __shfl_xor_sync(0xffffffffu, sum, 2);
                lrow[mf][r] = lrow[mf][r] * f + sum;
                #pragma unroll
                for (int j = 0; j < 8; j++) {
                    accO[mf][j][2*r]   *= f;
                    accO[mf][j][2*r+1] *= f;
                }
            }
        }

        #pragma unroll
        for (int kc = 0; kc < 4; kc++) {
            uint32_t pah[2][4], pal[2][4];
            #pragma unroll
            for (int mf = 0; mf < 2; mf++) {
                pack_hl(sc[mf][2*kc][0],   sc[mf][2*kc][1],   pah[mf][0], pal[mf][0]);
                pack_hl(sc[mf][2*kc][2],   sc[mf][2*kc][3],   pah[mf][1], pal[mf][1]);
                pack_hl(sc[mf][2*kc+1][0], sc[mf][2*kc+1][1], pah[mf][2], pal[mf][2]);
                pack_hl(sc[mf][2*kc+1][2], sc[mf][2*kc+1][3], pah[mf][3], pal[mf][3]);
            }
            #pragma unroll
            for (int nd = 0; nd < 4; nd++) {
                uint32_t vh[4], vl[4];
                const uint32_t vo = (uint32_t)(((kc * 16 + lane16) * AQS
                                               + nd * 16 + lane8) * 2);
                LDSM_X4T(vh[0], vh[1], vh[2], vh[3], vsh + vo);
                LDSM_X4T(vl[0], vl[1], vl[2], vl[3], vsl + vo);
                #pragma unroll
                for (int mf = 0; mf < 2; mf++) {
                    MMA16816(accO[mf][nd*2],   pah[mf], vh[0], vh[1]);
                    MMA16816(accO[mf][nd*2],   pah[mf], vl[0], vl[1]);
                    MMA16816(accO[mf][nd*2],   pal[mf], vh[0], vh[1]);
                    MMA16816(accO[mf][nd*2+1], pah[mf], vh[2], vh[3]);
                    MMA16816(accO[mf][nd*2+1], pah[mf], vl[2], vl[3]);
                    MMA16816(accO[mf][nd*2+1], pal[mf], vh[2], vh[3]);
                }
            }
        }
        __syncthreads();
    }

    #pragma unroll
    for (int mf = 0; mf < 2; mf++) {
        #pragma unroll
        for (int r = 0; r < 2; r++) {
            const float inv = 1.0f / lrow[mf][r];
            const int qrow = q0 + wid * 32 + mf * 16 + g + r * 8;
            const size_t base = ((size_t)(b * S_LEN + qrow)) * D_MODEL + h * DK + t2;
            #pragma unroll
            for (int j = 0; j < 8; j++) {
                uint32_t hw, lw;
                pack_hl(accO[mf][j][2*r] * inv, accO[mf][j][2*r+1] * inv, hw, lw);
                *(uint32_t*)(Oh + base + j * 8) = hw;
                *(uint32_t*)(Ol + base + j * 8) = lw;
            }
        }
    }
}

// ---------------- launch ---------------------------------------------------
extern "C" void kernel_launch(void* const* d_in, const int* in_sizes, int n_in,
                              void* d_out, int out_size)
{
    const float* x   = (const float*)d_in[0];
    const int*   msk = (const int*)  d_in[1];
    const float* wq  = (const float*)d_in[2];
    const float* bq  = (const float*)d_in[3];
    const float* wk  = (const float*)d_in[4];
    const float* bk  = (const float*)d_in[5];
    const float* wv  = (const float*)d_in[6];
    const float* bv  = (const float*)d_in[7];
    const float* wo  = (const float*)d_in[8];
    const float* bo  = (const float*)d_in[9];
    const float* w1  = (const float*)d_in[10];
    const float* b1  = (const float*)d_in[11];
    const float* w2  = (const float*)d_in[12];
    const float* b2  = (const float*)d_in[13];
    const float* l1a = (const float*)d_in[14];
    const float* l1b = (const float*)d_in[15];
    const float* l2a = (const float*)d_in[16];
    const float* l2b = (const float*)d_in[17];
    float* out = (float*)d_out;

    bf16 *xnh, *xnl, *qkvh, *qkvl, *ctxh, *ctxl, *wqkvh, *wqkvl, *woh, *wol;
    int8_t *xn28h, *xn28l, *mid8h, *mid8l, *w18h, *w18l, *w28h, *w28l;
    float *hbuf, *bqkv;
    cudaGetSymbolAddress((void**)&xnh,   g_xn_h);
    cudaGetSymbolAddress((void**)&xnl,   g_xn_l);
    cudaGetSymbolAddress((void**)&qkvh,  g_qkv_h);
    cudaGetSymbolAddress((void**)&qkvl,  g_qkv_l);
    cudaGetSymbolAddress((void**)&ctxh,  g_ctx_h);
    cudaGetSymbolAddress((void**)&ctxl,  g_ctx_l);
    cudaGetSymbolAddress((void**)&hbuf,  g_hbuf);
    cudaGetSymbolAddress((void**)&xn28h, g_xn28h);
    cudaGetSymbolAddress((void**)&xn28l, g_xn28l);
    cudaGetSymbolAddress((void**)&mid8h, g_mid8h);
    cudaGetSymbolAddress((void**)&mid8l, g_mid8l);
    cudaGetSymbolAddress((void**)&wqkvh, g_wqkv_h);
    cudaGetSymbolAddress((void**)&wqkvl, g_wqkv_l);
    cudaGetSymbolAddress((void**)&bqkv,  g_bqkv);
    cudaGetSymbolAddress((void**)&woh,   g_wo_h);
    cudaGetSymbolAddress((void**)&wol,   g_wo_l);
    cudaGetSymbolAddress((void**)&w18h,  g_w18h);
    cudaGetSymbolAddress((void**)&w18l,  g_w18l);
    cudaGetSymbolAddress((void**)&w28h,  g_w28h);
    cudaGetSymbolAddress((void**)&w28l,  g_w28l);

    cudaFuncSetAttribute((const void*)mma_gemm<false,true>,
        cudaFuncAttributeMaxDynamicSharedMemorySize, GEMM_SMEM);
    cudaFuncSetAttribute((const void*)mma_gemm<true,false>,
        cudaFuncAttributeMaxDynamicSharedMemorySize, GEMM_SMEM);
    cudaFuncSetAttribute((const void*)qgemm<true,false,true>,
        cudaFuncAttributeMaxDynamicSharedMemorySize, QGEMM_SMEM);
    cudaFuncSetAttribute((const void*)qgemm<false,true,false>,
        cudaFuncAttributeMaxDynamicSharedMemorySize, QGEMM_SMEM);
    cudaFuncSetAttribute(attn_mma,
        cudaFuncAttributeMaxDynamicSharedMemorySize, ATTN_SMEM_B);

    // weight prep
    split_qkv_kernel<<<(D_MODEL * QKV_N) / 1024, 256>>>(
        wq, wk, wv, bq, bk, bv, wqkvh, wqkvl, bqkv);
    split_wo_kernel<<<(D_MODEL * D_MODEL) / 1024, 256>>>(wo, woh, wol);
    quantw_kernel<<<(D_MODEL / 4) * F_FFN / 256, 256>>>(w1, w18h, w18l, F_FFN, W1_IS, W1_S);
    quantw_kernel<<<(F_FFN / 4) * D_MODEL / 256, 256>>>(w2, w28h, w28l, D_MODEL, W2_IS, W2_S);

    // ln1 -> bf16 hi/lo
    ln_split_kernel<<<M_ROWS, 256>>>(x, l1a, l1b, xnh, xnl);
    // QKV (bf16)
    mma_gemm<false,true><<<dim3(QKV_N/128, M_ROWS/128), 256, GEMM_SMEM>>>(
        xnh, xnl, wqkvh, wqkvl, bqkv, nullptr, nullptr, qkvh, qkvl,
        M_ROWS, QKV_N, D_MODEL);
    // attention
    attn_mma<<<dim3(S_LEN/256, N_HEADS, B_SZ), 256, ATTN_SMEM_B>>>(
        qkvh, qkvl, msk, ctxh, ctxl);
    // o-proj + residual(x) -> hbuf (fp32)
    mma_gemm<true,false><<<dim3(D_MODEL/128, M_ROWS/128), 256, GEMM_SMEM>>>(
        ctxh, ctxl, woh, wol, bo, x, hbuf, nullptr, nullptr, M_ROWS, D_MODEL, D_MODEL);
    // ln2 -> int8 hi/lo
    ln_quant_kernel<<<M_ROWS, 256>>>(hbuf, l2a, l2b, xn28h, xn28l);
    // FFN up (int8) + relu -> int8 hi/lo
    qgemm<true,false,true><<<dim3(F_FFN/64, M_ROWS/128), 256, QGEMM_SMEM>>>(
        xn28h, xn28l, w18h, w18l, b1, nullptr, nullptr, mid8h, mid8l,
        ACT_S * W1_S, M_ROWS, F_FFN, D_MODEL);
    // FFN down (int8) + residual(hbuf) -> out (fp32)
    qgemm<false,true,false><<<dim3(D_MODEL/64, M_ROWS/128), 256, QGEMM_SMEM>>>(
        mid8h, mid8l, w28h, w28l, b2, hbuf, out, nullptr, nullptr,
        ACT_S * W2_S, M_ROWS, D_MODEL, F_FFN);
}

// round 17
// speedup vs baseline: 1.6969x; 1.6969x over previous
#include <cuda_runtime.h>
#include <cuda_bf16.h>
#include <math.h>
#include <stdint.h>

#define D_MODEL 1024
#define F_FFN   4096
#define B_SZ    4
#define S_LEN   2048
#define N_HEADS 16
#define DK      64
#define M_ROWS  (B_SZ * S_LEN)
#define LN_EPS  1e-6f
#define QKV_N   3072

typedef __nv_bfloat16 bf16;

// ---------------- scratch ----------------
__device__ bf16 g_xn_h [(size_t)M_ROWS * D_MODEL];
__device__ bf16 g_xn_l [(size_t)M_ROWS * D_MODEL];
__device__ bf16 g_qkv_h[(size_t)M_ROWS * QKV_N];
__device__ bf16 g_qkv_l[(size_t)M_ROWS * QKV_N];
__device__ bf16 g_ctx_h[(size_t)M_ROWS * D_MODEL];
__device__ bf16 g_ctx_l[(size_t)M_ROWS * D_MODEL];
__device__ float g_hbuf[(size_t)M_ROWS * D_MODEL];
__device__ bf16 g_xn2_h[(size_t)M_ROWS * D_MODEL];
__device__ bf16 g_xn2_l[(size_t)M_ROWS * D_MODEL];
__device__ bf16 g_mid_h[(size_t)M_ROWS * F_FFN];
__device__ bf16 g_mid_l[(size_t)M_ROWS * F_FFN];
__device__ bf16 g_wqkv_h[(size_t)D_MODEL * QKV_N];
__device__ bf16 g_wqkv_l[(size_t)D_MODEL * QKV_N];
__device__ float g_bqkv[QKV_N];
__device__ bf16 g_wo_h[(size_t)D_MODEL * D_MODEL];
__device__ bf16 g_wo_l[(size_t)D_MODEL * D_MODEL];
__device__ bf16 g_w1_h[(size_t)D_MODEL * F_FFN];
__device__ bf16 g_w1_l[(size_t)D_MODEL * F_FFN];
__device__ bf16 g_w2_h[(size_t)F_FFN * D_MODEL];
__device__ bf16 g_w2_l[(size_t)F_FFN * D_MODEL];

// ---------------- helpers ----------------
__device__ __forceinline__ uint32_t smem_u32(const void* p) {
    return (uint32_t)__cvta_generic_to_shared(p);
}
#define LDSM_X4(r0,r1,r2,r3,addr) \
    asm volatile("ldmatrix.sync.aligned.m8n8.x4.shared.b16 {%0,%1,%2,%3},[%4];" \
        : "=r"(r0), "=r"(r1), "=r"(r2), "=r"(r3) : "r"(addr))
#define LDSM_X4T(r0,r1,r2,r3,addr) \
    asm volatile("ldmatrix.sync.aligned.m8n8.x4.trans.shared.b16 {%0,%1,%2,%3},[%4];" \
        : "=r"(r0), "=r"(r1), "=r"(r2), "=r"(r3) : "r"(addr))
#define MMA16816(c,a,b0,b1) \
    asm volatile("mma.sync.aligned.m16n8k16.row.col.f32.bf16.bf16.f32 " \
        "{%0,%1,%2,%3},{%4,%5,%6,%7},{%8,%9},{%0,%1,%2,%3};" \
        : "+f"((c)[0]), "+f"((c)[1]), "+f"((c)[2]), "+f"((c)[3]) \
        : "r"((a)[0]), "r"((a)[1]), "r"((a)[2]), "r"((a)[3]), "r"(b0), "r"(b1))
#define CP16(dst, src) \
    asm volatile("cp.async.cg.shared.global [%0],[%1],16;" :: "r"(dst), "l"(src))
#define CP_COMMIT asm volatile("cp.async.commit_group;")
#define CP_WAIT1  asm volatile("cp.async.wait_group 1;")
#define CP_WAIT0  asm volatile("cp.async.wait_group 0;")

__device__ __forceinline__ void split2(float x, bf16& h, bf16& l) {
    h = __float2bfloat16(x);
    l = __float2bfloat16(x - __bfloat162float(h));
}
__device__ __forceinline__ void pack_hl(float x, float y, uint32_t& h, uint32_t& l) {
    bf16 hx, lx, hy, ly;
    split2(x, hx, lx); split2(y, hy, ly);
    __nv_bfloat162 hp = __halves2bfloat162(hx, hy);
    __nv_bfloat162 lp = __halves2bfloat162(lx, ly);
    h = *(uint32_t*)&hp; l = *(uint32_t*)&lp;
}
__device__ __forceinline__ void split_store4(const float4 f, bf16* oh, bf16* ol) {
    __align__(8) bf16 h4[4], l4[4];
    split2(f.x, h4[0], l4[0]); split2(f.y, h4[1], l4[1]);
    split2(f.z, h4[2], l4[2]); split2(f.w, h4[3], l4[3]);
    *(uint2*)oh = *(uint2*)h4; *(uint2*)ol = *(uint2*)l4;
}

// ---------------- weight prep ----------------
__global__ void __launch_bounds__(256) split_qkv_kernel(
    const float* __restrict__ wq, const float* __restrict__ wk,
    const float* __restrict__ wv,
    const float* __restrict__ bq, const float* __restrict__ bk,
    const float* __restrict__ bv,
    bf16* __restrict__ oh, bf16* __restrict__ ol, float* __restrict__ bqkv)
{
    const size_t gid = ((size_t)blockIdx.x * 256 + threadIdx.x) * 4;
    const int row = (int)(gid / QKV_N);
    const int col = (int)(gid % QKV_N);
    const float* src; int scol;
    if (col < 1024)      { src = wq; scol = col; }
    else if (col < 2048) { src = wk; scol = col - 1024; }
    else                 { src = wv; scol = col - 2048; }
    const float4 f = *(const float4*)(src + (size_t)row * D_MODEL + scol);
    split_store4(f, oh + gid, ol + gid);
    if (gid < QKV_N) {
        #pragma unroll
        for (int i = 0; i < 4; i++) {
            const int c = (int)gid + i;
            bqkv[c] = (c < 1024) ? bq[c] : ((c < 2048) ? bk[c - 1024] : bv[c - 2048]);
        }
    }
}

__global__ void __launch_bounds__(256) split_rest_kernel(
    const float* __restrict__ wo, const float* __restrict__ w1,
    const float* __restrict__ w2,
    bf16* __restrict__ oh_o, bf16* __restrict__ ol_o,
    bf16* __restrict__ oh_1, bf16* __restrict__ ol_1,
    bf16* __restrict__ oh_2, bf16* __restrict__ ol_2)
{
    const int blk = blockIdx.x;
    const float* src; bf16 *oh, *ol; size_t off;
    if (blk < 1024)       { src = wo; oh = oh_o; ol = ol_o; off = (size_t)blk * 1024; }
    else if (blk < 5120)  { src = w1; oh = oh_1; ol = ol_1; off = (size_t)(blk - 1024) * 1024; }
    else                  { src = w2; oh = oh_2; ol = ol_2; off = (size_t)(blk - 5120) * 1024; }
    const size_t i = off + (size_t)threadIdx.x * 4;
    const float4 f = *(const float4*)(src + i);
    split_store4(f, oh + i, ol + i);
}

// ---------------- LayerNorm -> bf16 hi/lo ----------------
__global__ void __launch_bounds__(256) ln_split_kernel(
    const float* __restrict__ x, const float* __restrict__ alpha,
    const float* __restrict__ beta, bf16* __restrict__ oh, bf16* __restrict__ ol)
{
    __shared__ float red[32];
    const int row = blockIdx.x, tid = threadIdx.x;
    const float4 v = ((const float4*)(x + (size_t)row * D_MODEL))[tid];
    float s  = v.x + v.y + v.z + v.w;
    float s2 = v.x*v.x + v.y*v.y + v.z*v.z + v.w*v.w;
    #pragma unroll
    for (int off = 16; off > 0; off >>= 1) {
        s  += __shfl_xor_sync(0xffffffffu, s,  off);
        s2 += __shfl_xor_sync(0xffffffffu, s2, off);
    }
    const int warp = tid >> 5;
    if ((tid & 31) == 0) { red[warp] = s; red[8 + warp] = s2; }
    __syncthreads();
    if (tid == 0) {
        float ts = 0.f, ts2 = 0.f;
        #pragma unroll
        for (int i = 0; i < 8; i++) { ts += red[i]; ts2 += red[8 + i]; }
        const float mean = ts * (1.0f / (float)D_MODEL);
        float var = (ts2 - (float)D_MODEL * mean * mean) * (1.0f / (float)(D_MODEL - 1));
        var = fmaxf(var, 0.0f);
        red[16] = mean;
        red[17] = 1.0f / (sqrtf(var) + LN_EPS);
    }
    __syncthreads();
    const float mean = red[16], inv = red[17];
    const float4 a = ((const float4*)alpha)[tid];
    const float4 b = ((const float4*)beta)[tid];
    float4 o;
    o.x = a.x * (v.x - mean) * inv + b.x;
    o.y = a.y * (v.y - mean) * inv + b.y;
    o.z = a.z * (v.z - mean) * inv + b.z;
    o.w = a.w * (v.w - mean) * inv + b.w;
    split_store4(o, oh + (size_t)row * D_MODEL + tid * 4,
                    ol + (size_t)row * D_MODEL + tid * 4);
}

// ---------------- bf16 GEMM (R12 config) ----------------
#define ASTR 40
#define BSTR 136
#define STAGE_A (128 * ASTR)
#define STAGE_B (32 * BSTR)
#define STAGE_ELEMS (2 * STAGE_A + 2 * STAGE_B)
#define GEMM_SMEM (2 * STAGE_ELEMS * 2)

template<bool RELU, bool RES, bool BF16OUT>
__global__ void __launch_bounds__(256, 2) mma_gemm(
    const bf16* __restrict__ Ah, const bf16* __restrict__ Al,
    const bf16* __restrict__ Bh, const bf16* __restrict__ Bl,
    const float* __restrict__ bias, const float* __restrict__ res,
    float* __restrict__ C, bf16* __restrict__ Ch, bf16* __restrict__ Cl,
    int M, int N, int K)
{
    extern __shared__ bf16 sm[];
    const int tid  = threadIdx.x;
    const int lane = tid & 31;
    const int wid  = tid >> 5;
    const int wm   = (wid & 3) * 32;
    const int wn   = (wid >> 2) * 64;
    const int bx = blockIdx.x, by = blockIdx.y;

    const bf16* Abh = Ah + (size_t)(by * 128) * K;
    const bf16* Abl = Al + (size_t)(by * 128) * K;
    const bf16* Bbh = Bh + bx * 128;
    const bf16* Bbl = Bl + bx * 128;

    const int a_row = tid >> 1, a_c = (tid & 1) * 16;
    const int b_row = tid >> 3, b_c = (tid & 7) * 16;

    const uint32_t s_base = smem_u32(sm);
    const uint32_t a_dst0 = (uint32_t)(a_row * ASTR + a_c) * 2;
    const uint32_t b_dst0 = (uint32_t)(2 * STAGE_A + b_row * BSTR + b_c) * 2;

    const int lane16 = lane & 15;
    const int lane8  = (lane >> 4) * 8;
    const uint32_t a_off = (uint32_t)(((wm + lane16) * ASTR + lane8) * 2);
    const uint32_t b_off = (uint32_t)((lane16 * BSTR + wn + lane8) * 2);

    float acc[2][8][4];
    #pragma unroll
    for (int i = 0; i < 2; i++)
        #pragma unroll
        for (int j = 0; j < 8; j++)
            #pragma unroll
            for (int q = 0; q < 4; q++) acc[i][j][q] = 0.f;

    const int NT = K >> 5;
    {
        const uint32_t so = s_base;
        CP16(so + a_dst0,      Abh + (size_t)a_row * K + a_c);
        CP16(so + a_dst0 + 16, Abh + (size_t)a_row * K + a_c + 8);
        CP16(so + a_dst0 + STAGE_A * 2,      Abl + (size_t)a_row * K + a_c);
        CP16(so + a_dst0 + STAGE_A * 2 + 16, Abl + (size_t)a_row * K + a_c + 8);
        CP16(so + b_dst0,      Bbh + (size_t)b_row * N + b_c);
        CP16(so + b_dst0 + 16, Bbh + (size_t)b_row * N + b_c + 8);
        CP16(so + b_dst0 + STAGE_B * 2,      Bbl + (size_t)b_row * N + b_c);
        CP16(so + b_dst0 + STAGE_B * 2 + 16, Bbl + (size_t)b_row * N + b_c + 8);
        CP_COMMIT;
    }

    for (int t = 0; t < NT; t++) {
        if (t + 1 < NT) {
            const uint32_t so = s_base + (uint32_t)(((t + 1) & 1) * STAGE_ELEMS * 2);
            const int kt = (t + 1) * 32;
            CP16(so + a_dst0,      Abh + (size_t)a_row * K + kt + a_c);
            CP16(so + a_dst0 + 16, Abh + (size_t)a_row * K + kt + a_c + 8);
            CP16(so + a_dst0 + STAGE_A * 2,      Abl + (size_t)a_row * K + kt + a_c);
            CP16(so + a_dst0 + STAGE_A * 2 + 16, Abl + (size_t)a_row * K + kt + a_c + 8);
            CP16(so + b_dst0,      Bbh + (size_t)(kt + b_row) * N + b_c);
            CP16(so + b_dst0 + 16, Bbh + (size_t)(kt + b_row) * N + b_c + 8);
            CP16(so + b_dst0 + STAGE_B * 2,      Bbl + (size_t)(kt + b_row) * N + b_c);
            CP16(so + b_dst0 + STAGE_B * 2 + 16, Bbl + (size_t)(kt + b_row) * N + b_c + 8);
            CP_COMMIT;
            CP_WAIT1;
        } else {
            CP_WAIT0;
        }
        __syncthreads();

        const uint32_t ash = s_base + (uint32_t)((t & 1) * STAGE_ELEMS * 2);
        const uint32_t asl = ash + STAGE_A * 2;
        const uint32_t bsh = asl + STAGE_A * 2;
        const uint32_t bsl = bsh + STAGE_B * 2;

        #pragma unroll
        for (int ks = 0; ks < 2; ks++) {
            uint32_t ahf[2][4], alf[2][4];
            #pragma unroll
            for (int mf = 0; mf < 2; mf++) {
                const uint32_t ao = a_off + (uint32_t)((mf * 16 * ASTR + ks * 16) * 2);
                LDSM_X4(ahf[mf][0], ahf[mf][1], ahf[mf][2], ahf[mf][3], ash + ao);
                LDSM_X4(alf[mf][0], alf[mf][1], alf[mf][2], alf[mf][3], asl + ao);
            }
            #pragma unroll
            for (int nf2 = 0; nf2 < 4; nf2++) {
                uint32_t bh[4], bl[4];
                const uint32_t bo = b_off + (uint32_t)((ks * 16 * BSTR + nf2 * 16) * 2);
                LDSM_X4T(bh[0], bh[1], bh[2], bh[3], bsh + bo);
                LDSM_X4T(bl[0], bl[1], bl[2], bl[3], bsl + bo);
                #pragma unroll
                for (int mf = 0; mf < 2; mf++) {
                    #pragma unroll
                    for (int hh = 0; hh < 2; hh++) {
                        float* c = acc[mf][nf2 * 2 + hh];
                        MMA16816(c, ahf[mf], bh[2 * hh], bh[2 * hh + 1]);
                        MMA16816(c, ahf[mf], bl[2 * hh], bl[2 * hh + 1]);
                        MMA16816(c, alf[mf], bh[2 * hh], bh[2 * hh + 1]);
                    }
                }
            }
        }
        __syncthreads();
    }

    const int g = lane >> 2, t4 = lane & 3;
    #pragma unroll
    for (int mf = 0; mf < 2; mf++) {
        #pragma unroll
        for (int nf = 0; nf < 8; nf++) {
            const int col = bx * 128 + wn + nf * 8 + t4 * 2;
            const float2 bb = *(const float2*)(bias + col);
            #pragma unroll
            for (int half = 0; half < 2; half++) {
                const size_t r = (size_t)(by * 128 + wm + mf * 16 + g + half * 8);
                float2 o;
                o.x = acc[mf][nf][half * 2 + 0] + bb.x;
                o.y = acc[mf][nf][half * 2 + 1] + bb.y;
                if (RES) {
                    const float2 rv = *(const float2*)(res + r * N + col);
                    o.x += rv.x; o.y += rv.y;
                }
                if (RELU) { o.x = fmaxf(o.x, 0.f); o.y = fmaxf(o.y, 0.f); }
                if (BF16OUT) {
                    uint32_t hw, lw;
                    pack_hl(o.x, o.y, hw, lw);
                    *(uint32_t*)(Ch + r * N + col) = hw;
                    *(uint32_t*)(Cl + r * N + col) = lw;
                } else {
                    *(float2*)(C + r * N + col) = o;
                }
            }
        }
    }
}

// ---------------- flash attention: 128-row Q, 2-stage KV, 2 CTAs/SM ----------
#define AQS 72
#define Q_BYTES   (128 * AQS * 2)            // 18,432 per hi/lo
#define KV_MAT    (64 * AQS * 2)             // 9,216
#define KV_STAGE  (4 * KV_MAT)               // 36,864
#define MS_OFF    (2 * Q_BYTES + 2 * KV_STAGE)
#define ATTN_SMEM_B (MS_OFF + 2 * 64 * 4)    // 111,104 B -> 2 CTAs/SM

__global__ void __launch_bounds__(256, 2) attn_mma(
    const bf16* __restrict__ QKVh, const bf16* __restrict__ QKVl,
    const int* __restrict__ mask,
    bf16* __restrict__ Oh, bf16* __restrict__ Ol)
{
    extern __shared__ char smraw[];
    const uint32_t s_base = smem_u32(smraw);
    bf16* Qhs = (bf16*)smraw;
    bf16* Qls = (bf16*)(smraw + Q_BYTES);

    const int b  = blockIdx.z;
    const int h  = blockIdx.y;
    const int q0 = blockIdx.x * 128;
    const int tid  = threadIdx.x;
    const int lane = tid & 31;
    const int wid  = tid >> 5;
    const int lane16 = lane & 15;
    const int lane8  = (lane >> 4) * 8;
    const int g  = lane >> 2;
    const int t2 = (lane & 3) * 2;

    const bf16* Qh = QKVh;
    const bf16* Ql = QKVl;
    const bf16* Kh = QKVh + 1024;
    const bf16* Kl = QKVl + 1024;
    const bf16* Vh = QKVh + 2048;
    const bf16* Vl = QKVl + 2048;

    const uint32_t qsh = s_base;
    const uint32_t qsl = s_base + Q_BYTES;

    const int kv_r = tid >> 2;
    const int kv_c = (tid & 3) * 16;
    const uint32_t kv_dst0 = (uint32_t)((kv_r * AQS + kv_c) * 2);

    // prologue: stage 0
    {
        const uint32_t so = s_base + 2 * Q_BYTES;
        const size_t go = ((size_t)(b * S_LEN + kv_r)) * QKV_N + h * DK + kv_c;
        #pragma unroll
        for (int i = 0; i < 2; i++) {
            CP16(so + kv_dst0 + i * 16,              Kh + go + i * 8);
            CP16(so + KV_MAT + kv_dst0 + i * 16,     Kl + go + i * 8);
            CP16(so + 2 * KV_MAT + kv_dst0 + i * 16, Vh + go + i * 8);
            CP16(so + 3 * KV_MAT + kv_dst0 + i * 16, Vl + go + i * 8);
        }
        if (tid < 16)
            CP16(s_base + MS_OFF + (uint32_t)(tid * 16), mask + b * S_LEN + tid * 4);
        CP_COMMIT;
    }

    // stage Q tile (128 x 64)
    {
        const int r  = tid >> 1;
        const int c0 = (tid & 1) * 32;
        const size_t go = ((size_t)(b * S_LEN + q0 + r)) * QKV_N + h * DK + c0;
        #pragma unroll
        for (int i = 0; i < 4; i++) {
            *(uint4*)&Qhs[r * AQS + c0 + i * 8] = *(const uint4*)(Qh + go + i * 8);
            *(uint4*)&Qls[r * AQS + c0 + i * 8] = *(const uint4*)(Ql + go + i * 8);
        }
    }

    float accO[8][4];
    #pragma unroll
    for (int j = 0; j < 8; j++)
        #pragma unroll
        for (int q = 0; q < 4; q++) accO[j][q] = 0.f;
    float mrow[2] = {-1e30f, -1e30f};
    float lrow[2] = {0.f, 0.f};

    const int NTK = S_LEN / 64;   // 32

    for (int t = 0; t < NTK; t++) {
        if (t + 1 < NTK) {
            const uint32_t so = s_base + 2 * Q_BYTES + (uint32_t)(((t + 1) & 1) * KV_STAGE);
            const int kt = (t + 1) * 64;
            const size_t go = ((size_t)(b * S_LEN + kt + kv_r)) * QKV_N + h * DK + kv_c;
            #pragma unroll
            for (int i = 0; i < 2; i++) {
                CP16(so + kv_dst0 + i * 16,              Kh + go + i * 8);
                CP16(so + KV_MAT + kv_dst0 + i * 16,     Kl + go + i * 8);
                CP16(so + 2 * KV_MAT + kv_dst0 + i * 16, Vh + go + i * 8);
                CP16(so + 3 * KV_MAT + kv_dst0 + i * 16, Vl + go + i * 8);
            }
            if (tid < 16)
                CP16(s_base + MS_OFF + (uint32_t)(((t + 1) & 1) * 256 + tid * 16),
                     mask + b * S_LEN + kt + tid * 4);
            CP_COMMIT;
            CP_WAIT1;
        } else {
            CP_WAIT0;
        }
        __syncthreads();

        const int st = t & 1;
        const uint32_t ksh = s_base + 2 * Q_BYTES + (uint32_t)(st * KV_STAGE);
        const uint32_t ksl = ksh + KV_MAT;
        const uint32_t vsh = ksl + KV_MAT;
        const uint32_t vsl = vsh + KV_MAT;
        const int* Msi = (const int*)(smraw + MS_OFF + st * 256);

        // ---- S = Q K^T : per-warp 16 x 64 (Q frags reloaded per kc) ----
        float sc[8][4];
        #pragma unroll
        for (int j = 0; j < 8; j++)
            #pragma unroll
            for (int q = 0; q < 4; q++) sc[j][q] = 0.f;

        #pragma unroll
        for (int kc = 0; kc < 4; kc++) {
            uint32_t qh[4], ql[4];
            const uint32_t qo = (uint32_t)(((wid * 16 + lane16) * AQS
                                           + kc * 16 + lane8) * 2);
            LDSM_X4(qh[0], qh[1], qh[2], qh[3], qsh + qo);
            LDSM_X4(ql[0], ql[1], ql[2], ql[3], qsl + qo);
            #pragma unroll
            for (int np = 0; np < 4; np++) {
                uint32_t kh[4], kl[4];
                const uint32_t ko = (uint32_t)(((np * 16 + lane16) * AQS
                                               + kc * 16 + lane8) * 2);
                LDSM_X4(kh[0], kh[1], kh[2], kh[3], ksh + ko);
                LDSM_X4(kl[0], kl[1], kl[2], kl[3], ksl + ko);
                MMA16816(sc[2*np],   qh, kh[0], kh[2]);
                MMA16816(sc[2*np],   qh, kl[0], kl[2]);
                MMA16816(sc[2*np],   ql, kh[0], kh[2]);
                MMA16816(sc[2*np+1], qh, kh[1], kh[3]);
                MMA16816(sc[2*np+1], qh, kl[1], kl[3]);
                MMA16816(sc[2*np+1], ql, kh[1], kh[3]);
            }
        }

        float mb0[8], mb1[8];
        #pragma unroll
        for (int j = 0; j < 8; j++) {
            mb0[j] = (Msi[j * 8 + t2]     == 0) ? -1e9f : 0.f;
            mb1[j] = (Msi[j * 8 + t2 + 1] == 0) ? -1e9f : 0.f;
        }

        // ---- online softmax ----
        #pragma unroll
        for (int r = 0; r < 2; r++) {
            float mx = -1e30f;
            #pragma unroll
            for (int j = 0; j < 8; j++) {
                sc[j][2*r]   = sc[j][2*r]   * 0.125f + mb0[j];
                sc[j][2*r+1] = sc[j][2*r+1] * 0.125f + mb1[j];
                mx = fmaxf(mx, fmaxf(sc[j][2*r], sc[j][2*r+1]));
            }
            mx = fmaxf(mx, __shfl_xor_sync(0xffffffffu, mx, 1));
            mx = fmaxf(mx, __shfl_xor_sync(0xffffffffu, mx, 2));
            const float nm = fmaxf(mrow[r], mx);
            const float f  = __expf(mrow[r] - nm);
            mrow[r] = nm;
            float sum = 0.f;
            #pragma unroll
            for (int j = 0; j < 8; j++) {
                sc[j][2*r]   = __expf(sc[j][2*r]   - nm);
                sc[j][2*r+1] = __expf(sc[j][2*r+1] - nm);
                sum += sc[j][2*r] + sc[j][2*r+1];
            }
            sum += __shfl_xor_sync(0xffffffffu, sum, 1);
            sum += __shfl_xor_sync(0xffffffffu, sum, 2);
            lrow[r] = lrow[r] * f + sum;
            #pragma unroll
            for (int j = 0; j < 8; j++) {
                accO[j][2*r]   *= f;
                accO[j][2*r+1] *= f;
            }
        }

        // ---- O += P @ V ----
        #pragma unroll
        for (int kc = 0; kc < 4; kc++) {
            uint32_t pah[4], pal[4];
            pack_hl(sc[2*kc][0],   sc[2*kc][1],   pah[0], pal[0]);
            pack_hl(sc[2*kc][2],   sc[2*kc][3],   pah[1], pal[1]);
            pack_hl(sc[2*kc+1][0], sc[2*kc+1][1], pah[2], pal[2]);
            pack_hl(sc[2*kc+1][2], sc[2*kc+1][3], pah[3], pal[3]);
            #pragma unroll
            for (int nd = 0; nd < 4; nd++) {
                uint32_t vh[4], vl[4];
                const uint32_t vo = (uint32_t)(((kc * 16 + lane16) * AQS
                                               + nd * 16 + lane8) * 2);
                LDSM_X4T(vh[0], vh[1], vh[2], vh[3], vsh + vo);
                LDSM_X4T(vl[0], vl[1], vl[2], vl[3], vsl + vo);
                MMA16816(accO[nd*2],   pah, vh[0], vh[1]);
                MMA16816(accO[nd*2],   pah, vl[0], vl[1]);
                MMA16816(accO[nd*2],   pal, vh[0], vh[1]);
                MMA16816(accO[nd*2+1], pah, vh[2], vh[3]);
                MMA16816(accO[nd*2+1], pah, vl[2], vl[3]);
                MMA16816(accO[nd*2+1], pal, vh[2], vh[3]);
            }
        }
        __syncthreads();
    }

    #pragma unroll
    for (int r = 0; r < 2; r++) {
        const float inv = 1.0f / lrow[r];
        const int qrow = q0 + wid * 16 + g + r * 8;
        const size_t base = ((size_t)(b * S_LEN + qrow)) * D_MODEL + h * DK + t2;
        #pragma unroll
        for (int j = 0; j < 8; j++) {
            uint32_t hw, lw;
            pack_hl(accO[j][2*r] * inv, accO[j][2*r+1] * inv, hw, lw);
            *(uint32_t*)(Oh + base + j * 8) = hw;
            *(uint32_t*)(Ol + base + j * 8) = lw;
        }
    }
}

// ---------------- launch ---------------------------------------------------
extern "C" void kernel_launch(void* const* d_in, const int* in_sizes, int n_in,
                              void* d_out, int out_size)
{
    const float* x   = (const float*)d_in[0];
    const int*   msk = (const int*)  d_in[1];
    const float* wq  = (const float*)d_in[2];
    const float* bq  = (const float*)d_in[3];
    const float* wk  = (const float*)d_in[4];
    const float* bk  = (const float*)d_in[5];
    const float* wv  = (const float*)d_in[6];
    const float* bv  = (const float*)d_in[7];
    const float* wo  = (const float*)d_in[8];
    const float* bo  = (const float*)d_in[9];
    const float* w1  = (const float*)d_in[10];
    const float* b1  = (const float*)d_in[11];
    const float* w2  = (const float*)d_in[12];
    const float* b2  = (const float*)d_in[13];
    const float* l1a = (const float*)d_in[14];
    const float* l1b = (const float*)d_in[15];
    const float* l2a = (const float*)d_in[16];
    const float* l2b = (const float*)d_in[17];
    float* out = (float*)d_out;

    bf16 *xnh, *xnl, *qkvh, *qkvl, *ctxh, *ctxl, *xn2h, *xn2l, *midh, *midl;
    bf16 *wqkvh, *wqkvl, *woh, *wol, *w1h, *w1l, *w2h, *w2l;
    float *hbuf, *bqkv;
    cudaGetSymbolAddress((void**)&xnh,   g_xn_h);
    cudaGetSymbolAddress((void**)&xnl,   g_xn_l);
    cudaGetSymbolAddress((void**)&qkvh,  g_qkv_h);
    cudaGetSymbolAddress((void**)&qkvl,  g_qkv_l);
    cudaGetSymbolAddress((void**)&ctxh,  g_ctx_h);
    cudaGetSymbolAddress((void**)&ctxl,  g_ctx_l);
    cudaGetSymbolAddress((void**)&hbuf,  g_hbuf);
    cudaGetSymbolAddress((void**)&xn2h,  g_xn2_h);
    cudaGetSymbolAddress((void**)&xn2l,  g_xn2_l);
    cudaGetSymbolAddress((void**)&midh,  g_mid_h);
    cudaGetSymbolAddress((void**)&midl,  g_mid_l);
    cudaGetSymbolAddress((void**)&wqkvh, g_wqkv_h);
    cudaGetSymbolAddress((void**)&wqkvl, g_wqkv_l);
    cudaGetSymbolAddress((void**)&bqkv,  g_bqkv);
    cudaGetSymbolAddress((void**)&woh,   g_wo_h);
    cudaGetSymbolAddress((void**)&wol,   g_wo_l);
    cudaGetSymbolAddress((void**)&w1h,   g_w1_h);
    cudaGetSymbolAddress((void**)&w1l,   g_w1_l);
    cudaGetSymbolAddress((void**)&w2h,   g_w2_h);
    cudaGetSymbolAddress((void**)&w2l,   g_w2_l);

    cudaFuncSetAttribute((const void*)mma_gemm<false,false,true>,
        cudaFuncAttributeMaxDynamicSharedMemorySize, GEMM_SMEM);
    cudaFuncSetAttribute((const void*)mma_gemm<false,true,false>,
        cudaFuncAttributeMaxDynamicSharedMemorySize, GEMM_SMEM);
    cudaFuncSetAttribute((const void*)mma_gemm<true,false,true>,
        cudaFuncAttributeMaxDynamicSharedMemorySize, GEMM_SMEM);
    cudaFuncSetAttribute(attn_mma,
        cudaFuncAttributeMaxDynamicSharedMemorySize, ATTN_SMEM_B);

    split_qkv_kernel<<<(D_MODEL * QKV_N) / 1024, 256>>>(
        wq, wk, wv, bq, bk, bv, wqkvh, wqkvl, bqkv);
    split_rest_kernel<<<9216, 256>>>(
        wo, w1, w2, woh, wol, w1h, w1l, w2h, w2l);
    ln_split_kernel<<<M_ROWS, 256>>>(x, l1a, l1b, xnh, xnl);
    mma_gemm<false,false,true><<<dim3(QKV_N/128, M_ROWS/128), 256, GEMM_SMEM>>>(
        xnh, xnl, wqkvh, wqkvl, bqkv, nullptr, nullptr, qkvh, qkvl,
        M_ROWS, QKV_N, D_MODEL);
    attn_mma<<<dim3(S_LEN/128, N_HEADS, B_SZ), 256, ATTN_SMEM_B>>>(
        qkvh, qkvl, msk, ctxh, ctxl);
    mma_gemm<false,true,false><<<dim3(D_MODEL/128, M_ROWS/128), 256, GEMM_SMEM>>>(
        ctxh, ctxl, woh, wol, bo, x, hbuf, nullptr, nullptr, M_ROWS, D_MODEL, D_MODEL);
    ln_split_kernel<<<M_ROWS, 256>>>(hbuf, l2a, l2b, xn2h, xn2l);
    mma_gemm<true,false,true><<<dim3(F_FFN/128, M_ROWS/128), 256, GEMM_SMEM>>>(
        xn2h, xn2l, w1h, w1l, b1, nullptr, nullptr, midh, midl, M_ROWS, F_FFN, D_MODEL);
    mma_gemm<false,true,false><<<dim3(D_MODEL/128, M_ROWS/128), 256, GEMM_SMEM>>>(
        midh, midl, w2h, w2l, b2, hbuf, out, nullptr, nullptr, M_ROWS, D_MODEL, F_FFN);
}